// round 17
// baseline (speedup 1.0000x reference)
#include <cuda_runtime.h>
#include <cuda_fp16.h>
#include <cstdint>

// ===========================================================================
// DensityMatrixMLP, fused fp16 HMMA, round 15.
// = round 12 (106.8us, known-good) with stage 3 register-blocked:
//   - thread caches its 8 L-rows in registers (base ii*(ii+P), compile-time)
//   - streams each L_j ONCE (136 LDS/thread vs ~650) -> dots are reg-reg FMA
//   - res[8][4] chunk buffer -> identical float4 gmem stores
// No new instructions, no layout changes, fp32 stage-3 math unchanged.
// ===========================================================================

#define THREADS 128
#define ROWS    64
#define TRIL    136
#define VS_STRIDE 137

// ---- smem layout (bytes) ---- (identical to round 12)
#define OFF_B1   0            // 128 f32
#define OFF_B2   512          // 136 f32
#define OFF_TR   1088         // 64 f32
#define OFF_A    2048         // 16 KB region (X / H fp16, 64 r x 128 k)
#define XH       (OFF_A)              // 64r x 256B
#define HH       (OFF_A)              // overlay after GEMM1
#define OFF_W    (OFF_A + 16384)      // 40 KB weight region
#define W1H      (OFF_W)              // 128k x 256B per chunk (32 KB used)
#define W2H      (OFF_W)              // overlay: 128k x 320B = 40960 B
#define OFF_VS   (OFF_A)              // Vs overlay: 64 x 137 f32 = 35072 B
#define SMEM_BYTES (OFF_W + 40960)    // 59392   (3 CTAs/SM: 178176)

// ---- pre-converted weights (fp16, swizzled, byte-identical to smem) ----
__device__ __align__(16) unsigned char g_w1h[256 * 256];   // [256k][256B]
__device__ __align__(16) unsigned char g_w2h[128 * 320];   // [128k][320B], n->144 pad

static __device__ __forceinline__ uint32_t smem_u32(const void* p) {
    uint32_t a;
    asm("{ .reg .u64 t; cvta.to.shared.u64 t, %1; cvt.u32.u64 %0, t; }"
        : "=r"(a) : "l"(p));
    return a;
}

static __device__ __forceinline__ uint32_t swz256(int row, int bc) {
    return (uint32_t)(row * 256 + ((((bc >> 4) ^ (row & 7)) << 4) | (bc & 15)));
}
static __device__ __forceinline__ uint32_t swz320(int row, int bc) {
    int c = bc >> 4;
    if (c < 16) c ^= (row & 7);
    return (uint32_t)(row * 320 + (c << 4) + (bc & 15));
}
static __device__ __forceinline__ uint32_t lm256(uint32_t base, int r0, int bc0, int lane) {
    int row = r0 + (lane & 15), bc = bc0 + ((lane >> 4) << 4);
    return base + swz256(row, bc);
}
static __device__ __forceinline__ uint32_t lm320(uint32_t base, int r0, int bc0, int lane) {
    int row = r0 + (lane & 15), bc = bc0 + ((lane >> 4) << 4);
    return base + swz320(row, bc);
}

static __device__ __forceinline__ void ldsm_x4(uint32_t a, uint32_t r[4]) {
    asm volatile("ldmatrix.sync.aligned.m8n8.x4.shared.b16 {%0,%1,%2,%3}, [%4];"
                 : "=r"(r[0]), "=r"(r[1]), "=r"(r[2]), "=r"(r[3]) : "r"(a));
}
static __device__ __forceinline__ void ldsm_x4t(uint32_t a, uint32_t r[4]) {
    asm volatile("ldmatrix.sync.aligned.m8n8.x4.trans.shared.b16 {%0,%1,%2,%3}, [%4];"
                 : "=r"(r[0]), "=r"(r[1]), "=r"(r[2]), "=r"(r[3]) : "r"(a));
}
static __device__ __forceinline__ void ldsm_x2t(uint32_t a, uint32_t r[2]) {
    asm volatile("ldmatrix.sync.aligned.m8n8.x2.trans.shared.b16 {%0,%1}, [%2];"
                 : "=r"(r[0]), "=r"(r[1]) : "r"(a));
}
static __device__ __forceinline__ void mma_f16(float d[4], const uint32_t a[4],
                                               const uint32_t* b) {
    asm volatile(
        "mma.sync.aligned.m16n8k16.row.col.f32.f16.f16.f32 "
        "{%0,%1,%2,%3}, {%4,%5,%6,%7}, {%8,%9}, {%0,%1,%2,%3};"
        : "+f"(d[0]), "+f"(d[1]), "+f"(d[2]), "+f"(d[3])
        : "r"(a[0]), "r"(a[1]), "r"(a[2]), "r"(a[3]), "r"(b[0]), "r"(b[1]));
}

#define CP16(dst, src) \
    asm volatile("cp.async.cg.shared.global [%0], [%1], 16;" :: "r"(dst), "l"(src))
#define CP_COMMIT() asm volatile("cp.async.commit_group;" ::: "memory")
#define CP_WAIT0()  asm volatile("cp.async.wait_group 0;" ::: "memory")

static __device__ __forceinline__ uint32_t h2u(__half2 v) {
    return *reinterpret_cast<uint32_t*>(&v);
}
static __device__ __forceinline__ uint4 cvt8(const float* v) {
    uint32_t p[4];
#pragma unroll
    for (int q = 0; q < 4; q++)
        p[q] = h2u(__floats2half2_rn(v[2*q], v[2*q+1]));
    return make_uint4(p[0], p[1], p[2], p[3]);
}

// ---- prep kernel: W1/W2 -> swizzled fp16 globals ----
__global__ void prep_weights(const float* __restrict__ W1,
                             const float* __restrict__ W2) {
    int t = blockIdx.x * blockDim.x + threadIdx.x;
    if (t < 32768) {                       // W1: [256k][128n]
        int k = t >> 7, n = t & 127;
        uint32_t off = (uint32_t)(k * 256 + ((((n >> 3) ^ (k & 7)) << 4) | ((n & 7) * 2)));
        *reinterpret_cast<__half*>(g_w1h + off) = __float2half_rn(W1[t]);
    } else if (t < 32768 + 128 * 144) {    // W2: [128k][144n], n>=136 pad zero
        int u = t - 32768;
        int k = u / 144, n = u - k * 144;
        float v = (n < TRIL) ? W2[k * TRIL + n] : 0.f;
        int c = n >> 3; if (c < 16) c ^= (k & 7);
        uint32_t off = (uint32_t)(k * 320 + (c << 4) + ((n & 7) * 2));
        *reinterpret_cast<__half*>(g_w2h + off) = __float2half_rn(v);
    }
}

// ---- stage 3, register-blocked: thread owns 8 rho-rows of parity P =========
// Li cache base for ii-th row (i = 2*ii+P): ii*(ii+P); total 64 (P=0)/72 (P=1).
template <int P>
static __device__ __forceinline__ void rho_parity(const float* __restrict__ vrow,
                                                  float invtr,
                                                  float* __restrict__ orow) {
    float Li[P ? 72 : 64];
#pragma unroll
    for (int ii = 0; ii < 8; ii++) {
        const int i = 2 * ii + P;
        const int ti = i * (i + 1) / 2;
        const int cb = ii * (ii + P);
#pragma unroll
        for (int k = 0; k <= i; k++) Li[cb + k] = vrow[ti + k];
    }
    float res[8][4];
#pragma unroll
    for (int j = 0; j < 16; j++) {
        const int tj = j * (j + 1) / 2;
        float Lj[16];
#pragma unroll
        for (int k = 0; k <= j; k++) Lj[k] = vrow[tj + k];
#pragma unroll
        for (int ii = 0; ii < 8; ii++) {
            const int i = 2 * ii + P;
            const int cb = ii * (ii + P);
            const int len = (j < i) ? j : i;
            float dot = 0.f;
#pragma unroll
            for (int k = 0; k <= len; k++) dot = fmaf(Li[cb + k], Lj[k], dot);
            res[ii][j & 3] = dot * invtr;
        }
        if ((j & 3) == 3) {
#pragma unroll
            for (int ii = 0; ii < 8; ii++) {
                const int i = 2 * ii + P;
                *reinterpret_cast<float4*>(&orow[i * 16 + (j - 3)]) =
                    make_float4(res[ii][0], res[ii][1], res[ii][2], res[ii][3]);
            }
        }
    }
}

__global__ void __launch_bounds__(THREADS, 3)
density_mlp_hmma(const float* __restrict__ x,
                 const float* __restrict__ b1,
                 const float* __restrict__ b2,
                 float* __restrict__ out) {
    extern __shared__ char smem[];
    const uint32_t sb = smem_u32(smem);
    const int tid  = threadIdx.x;
    const int wid  = tid >> 5;
    const int lane = tid & 31;
    const int brow = blockIdx.x * ROWS;

    float* bias1 = reinterpret_cast<float*>(smem + OFF_B1);
    float* bias2 = reinterpret_cast<float*>(smem + OFF_B2);
    float* trc   = reinterpret_cast<float*>(smem + OFF_TR);

    bias1[tid] = b1[tid];
    if (tid < ROWS) trc[tid] = 0.f;
    for (int i = tid; i < TRIL; i += THREADS) bias2[i] = b2[i];

    const int m0  = (wid >> 1) * 32;      // warp row base {0,32}
    const int n0g = (wid & 1) * 64;       // warp col base (GEMM1)

    // ======================= GEMM1: 2 K-chunks of 128 =======================
    float acc[2][8][4];
#pragma unroll
    for (int mt = 0; mt < 2; mt++)
#pragma unroll
    for (int nt = 0; nt < 8; nt++)
#pragma unroll
    for (int q = 0; q < 4; q++) acc[mt][nt][q] = 0.f;

    for (int c = 0; c < 2; c++) {
        if (c) __syncthreads();
        {
            const unsigned char* sh = g_w1h + c * 32768;
#pragma unroll
            for (int i = 0; i < 16; i++) {
                int u = (tid + i * THREADS) * 16;
                CP16(sb + W1H + u, sh + u);
            }
            CP_COMMIT();
        }
#pragma unroll
        for (int i = 0; i < 8; i++) {
            int u = tid + i * THREADS;
            int row = u >> 4, j = u & 15;
            const float* s = x + (size_t)(brow + row) * 256 + c * 128 + j * 8;
            float4 p = *reinterpret_cast<const float4*>(s);
            float4 q4 = *reinterpret_cast<const float4*>(s + 4);
            float v[8] = {p.x, p.y, p.z, p.w, q4.x, q4.y, q4.z, q4.w};
            *reinterpret_cast<uint4*>(smem + XH + swz256(row, j * 16)) = cvt8(v);
        }
        CP_WAIT0();
        __syncthreads();

#pragma unroll
        for (int kt = 0; kt < 8; kt++) {
            uint32_t ah[2][4];
            ldsm_x4(lm256(sb + XH, m0,      kt * 32, lane), ah[0]);
            ldsm_x4(lm256(sb + XH, m0 + 16, kt * 32, lane), ah[1]);
#pragma unroll
            for (int p = 0; p < 4; p++) {
                uint32_t th[4];
                ldsm_x4t(lm256(sb + W1H, kt * 16, (n0g + p * 16) * 2, lane), th);
#pragma unroll
                for (int mt = 0; mt < 2; mt++) {
                    mma_f16(acc[mt][2*p],   ah[mt], th);
                    mma_f16(acc[mt][2*p+1], ah[mt], th + 2);
                }
            }
        }
    }
    __syncthreads();

    // ============== epilogue 1: H = relu(C1+b1) -> HH (fp16) ================
    {
#pragma unroll
        for (int i = 0; i < 20; i++) {
            int u = (tid + i * THREADS) * 16;
            CP16(sb + W2H + u, g_w2h + u);
        }
        CP_COMMIT();
    }
#pragma unroll
    for (int mt = 0; mt < 2; mt++)
#pragma unroll
    for (int nt = 0; nt < 8; nt++) {
        int col = n0g + nt * 8 + ((lane & 3) << 1);
        float ba = bias1[col], bb = bias1[col + 1];
        int r = m0 + mt * 16 + (lane >> 2);
#pragma unroll
        for (int half = 0; half < 2; half++) {
            float v0 = fmaxf(acc[mt][nt][2*half]     + ba, 0.f);
            float v1 = fmaxf(acc[mt][nt][2*half + 1] + bb, 0.f);
            uint32_t off = swz256(r + half * 8, col * 2);
            *reinterpret_cast<uint32_t*>(smem + HH + off) =
                h2u(__floats2half2_rn(v0, v1));
        }
    }
    CP_WAIT0();
    __syncthreads();

    // ================= GEMM2: H @ W2, single pass over K=128 ================
    const int n0g2 = (wid & 1) * 72;
    float acc2[2][9][4];
#pragma unroll
    for (int mt = 0; mt < 2; mt++)
#pragma unroll
    for (int nt = 0; nt < 9; nt++)
#pragma unroll
    for (int q = 0; q < 4; q++) acc2[mt][nt][q] = 0.f;

#pragma unroll
    for (int kt = 0; kt < 8; kt++) {
        uint32_t ah[2][4];
        ldsm_x4(lm256(sb + HH, m0,      kt * 32, lane), ah[0]);
        ldsm_x4(lm256(sb + HH, m0 + 16, kt * 32, lane), ah[1]);
#pragma unroll
        for (int p = 0; p < 4; p++) {
            uint32_t th[4];
            ldsm_x4t(lm320(sb + W2H, kt * 16, (n0g2 + p * 16) * 2, lane), th);
#pragma unroll
            for (int mt = 0; mt < 2; mt++) {
                mma_f16(acc2[mt][2*p],   ah[mt], th);
                mma_f16(acc2[mt][2*p+1], ah[mt], th + 2);
            }
        }
        {
            uint32_t th8[2];
            ldsm_x2t(lm320(sb + W2H, kt * 16, (n0g2 + 64) * 2, lane), th8);
#pragma unroll
            for (int mt = 0; mt < 2; mt++)
                mma_f16(acc2[mt][8], ah[mt], th8);
        }
    }
    __syncthreads();                      // H/W2 regions reusable (Vs overlay)

    // ============ epilogue 2: V = C2+b2 -> Vs, trace ========================
    {
        float* Vs = reinterpret_cast<float*>(smem + OFF_VS);
        float part[2][2] = {{0.f, 0.f}, {0.f, 0.f}};
#pragma unroll
        for (int mt = 0; mt < 2; mt++)
#pragma unroll
        for (int nt = 0; nt < 9; nt++) {
            int col = n0g2 + nt * 8 + ((lane & 3) << 1);
            if (col < TRIL) {
                float ba = bias2[col];
                float bb = (col + 1 < TRIL) ? bias2[col + 1] : 0.f;
                int r = m0 + mt * 16 + (lane >> 2);
#pragma unroll
                for (int half = 0; half < 2; half++) {
                    float v0 = acc2[mt][nt][2*half] + ba;
                    Vs[(r + half*8) * VS_STRIDE + col] = v0;
                    part[mt][half] = fmaf(v0, v0, part[mt][half]);
                    if (col + 1 < TRIL) {
                        float v1 = acc2[mt][nt][2*half + 1] + bb;
                        Vs[(r + half*8) * VS_STRIDE + col + 1] = v1;
                        part[mt][half] = fmaf(v1, v1, part[mt][half]);
                    }
                }
            }
        }
#pragma unroll
        for (int mt = 0; mt < 2; mt++)
#pragma unroll
        for (int half = 0; half < 2; half++) {
            float s = part[mt][half];
            s += __shfl_xor_sync(0xFFFFFFFF, s, 1);
            s += __shfl_xor_sync(0xFFFFFFFF, s, 2);
            if ((lane & 3) == 0)
                atomicAdd(&trc[m0 + mt * 16 + (lane >> 2) + half * 8], s);
        }
    }
    __syncthreads();

    // ========== stage 3: rho = L L^T / trace (register-blocked) =============
    {
        const float* Vs = reinterpret_cast<const float*>(smem + OFF_VS);
        const int row = tid & (ROWS - 1);
        const int ib  = tid >> 6;             // 0: even i, 1: odd i
        const float* vrow = &Vs[row * VS_STRIDE];
        const float invtr = 1.0f / trc[row];
        float* orow = &out[(size_t)(brow + row) * 256];
        if (ib == 0) rho_parity<0>(vrow, invtr, orow);
        else         rho_parity<1>(vrow, invtr, orow);
    }
}

extern "C" void kernel_launch(void* const* d_in, const int* in_sizes, int n_in,
                              void* d_out, int out_size) {
    const float* x  = (const float*)d_in[0];
    const float* W1 = (const float*)d_in[1];
    const float* b1 = (const float*)d_in[2];
    const float* W2 = (const float*)d_in[3];
    const float* b2 = (const float*)d_in[4];
    float* out = (float*)d_out;

    const int batch  = in_sizes[0] / 256;   // 131072
    const int blocks = batch / ROWS;        // 2048

    prep_weights<<<200, 256>>>(W1, W2);

    cudaFuncSetAttribute(density_mlp_hmma,
                         cudaFuncAttributeMaxDynamicSharedMemorySize, SMEM_BYTES);
    density_mlp_hmma<<<blocks, THREADS, SMEM_BYTES>>>(x, b1, b2, out);
}